// round 12
// baseline (speedup 1.0000x reference)
#include <cuda_runtime.h>
#include <cuda_fp16.h>
#include <cstdint>
#include <cstddef>

#define BATCH 16
#define SEQN 2048
#define DIM 128
#define TQ 64
#define TK 64
#define NKT (SEQN / TK)   // 32
#define NTHREADS 128
#define LOG2E 1.4426950408889634f

// ---------------- scratch (fragment-ordered fp16 copies) ----------------
__device__ __align__(16) unsigned char g_QF[(size_t)16 * 128 * 8192];
__device__ __align__(16) unsigned char g_KF[(size_t)16 * 32 * 32768];
__device__ __align__(16) unsigned char g_VF[(size_t)16 * 32 * 16384];

__device__ __forceinline__ uint32_t packh(float x, float y) {
    __half2 h = __floats2half2_rn(x, y);
    return *reinterpret_cast<uint32_t*>(&h);
}
__device__ __forceinline__ void split(float x, float& hi, float& lo) {
    __half h = __float2half_rn(x);
    hi = __half2float(h);
    lo = x - hi;
}
__device__ __forceinline__ float ex2(float x) {
    float r; asm("ex2.approx.f32 %0, %1;" : "=f"(r) : "f"(x)); return r;
}

__device__ __forceinline__ void mma16816(float* c, const uint32_t* a, const uint32_t* b) {
    asm volatile(
        "mma.sync.aligned.m16n8k16.row.col.f32.f16.f16.f32 "
        "{%0,%1,%2,%3}, {%4,%5,%6,%7}, {%8,%9}, {%0,%1,%2,%3};"
        : "+f"(c[0]), "+f"(c[1]), "+f"(c[2]), "+f"(c[3])
        : "r"(a[0]), "r"(a[1]), "r"(a[2]), "r"(a[3]), "r"(b[0]), "r"(b[1]));
}

__device__ __forceinline__ void cp16(uint32_t saddr, const void* gaddr) {
    asm volatile("cp.async.cg.shared.global [%0], [%1], 16;" :: "r"(saddr), "l"(gaddr));
}
__device__ __forceinline__ uint32_t smem_u32(const void* p) {
    uint32_t a;
    asm("{ .reg .u64 t; cvta.to.shared.u64 t, %1; cvt.u32.u64 %0, t; }" : "=r"(a) : "l"(p));
    return a;
}

// ---------------- fused prep kernel (proven) ----------------

__device__ __forceinline__ void prep_q_body(const float* __restrict__ q, int tid) {
    int lane = tid & 31, kt = (tid >> 5) & 7, qt = (tid >> 8) & 127, b = tid >> 15;
    int g = lane >> 2, t = lane & 3;
    int row = qt * 16 + g, d0 = kt * 16 + t * 2;
    const float* qb = q + ((size_t)b * SEQN) * DIM;
    float2 x00 = *(const float2*)(qb + (size_t)row * DIM + d0);
    float2 x10 = *(const float2*)(qb + (size_t)(row + 8) * DIM + d0);
    float2 x01 = *(const float2*)(qb + (size_t)row * DIM + d0 + 8);
    float2 x11 = *(const float2*)(qb + (size_t)(row + 8) * DIM + d0 + 8);
    uint4 hi, lo;
    float l00x, l00y, l10x, l10y, l01x, l01y, l11x, l11y;
    float h00x, h00y, h10x, h10y, h01x, h01y, h11x, h11y;
    split(x00.x, h00x, l00x); split(x00.y, h00y, l00y);
    split(x10.x, h10x, l10x); split(x10.y, h10y, l10y);
    split(x01.x, h01x, l01x); split(x01.y, h01y, l01y);
    split(x11.x, h11x, l11x); split(x11.y, h11y, l11y);
    hi.x = packh(h00x, h00y); hi.y = packh(h10x, h10y);
    hi.z = packh(h01x, h01y); hi.w = packh(h11x, h11y);
    lo.x = packh(l00x, l00y); lo.y = packh(l10x, l10y);
    lo.z = packh(l01x, l01y); lo.w = packh(l11x, l11y);
    unsigned char* base = g_QF + ((size_t)(b * 128 + qt)) * 8192;
    *(uint4*)(base + (0 * 8 + kt) * 512 + lane * 16) = hi;
    *(uint4*)(base + (1 * 8 + kt) * 512 + lane * 16) = lo;
}

__device__ __forceinline__ void prep_k_body(const float* __restrict__ k, int tid) {
    int lane = tid & 31, nt = (tid >> 5) & 7, kt = (tid >> 8) & 7,
        tile = (tid >> 11) & 31, b = tid >> 16;
    int g = lane >> 2, t = lane & 3;
    int key = tile * 64 + nt * 8 + g, d0 = kt * 16 + t * 2;
    const float* kb = k + ((size_t)b * SEQN) * DIM;
    float2 f0 = *(const float2*)(kb + (size_t)key * DIM + d0);
    float2 f1 = *(const float2*)(kb + (size_t)key * DIM + d0 + 8);
    f0.x *= LOG2E; f0.y *= LOG2E; f1.x *= LOG2E; f1.y *= LOG2E;
    float h0x, l0x, h0y, l0y, h1x, l1x, h1y, l1y;
    split(f0.x, h0x, l0x); split(f0.y, h0y, l0y);
    split(f1.x, h1x, l1x); split(f1.y, h1y, l1y);
    uint2 hi = {packh(h0x, h0y), packh(h1x, h1y)};
    uint2 lo = {packh(l0x, l0y), packh(l1x, l1y)};
    unsigned char* base = g_KF + ((size_t)(b * 32 + tile)) * 32768;
    *(uint2*)(base + ((0 * 8 + kt) * 8 + nt) * 256 + lane * 8) = hi;
    *(uint2*)(base + ((1 * 8 + kt) * 8 + nt) * 256 + lane * 8) = lo;
}

__device__ __forceinline__ void prep_v_body(const float* __restrict__ v, int tid) {
    int lane = tid & 31, nt = (tid >> 5) & 15, kc = (tid >> 9) & 3,
        tile = (tid >> 11) & 31, b = tid >> 16;
    int g = lane >> 2, t = lane & 3;
    int k0 = tile * 64 + kc * 16 + t * 2, dim = nt * 8 + g;
    const float* vb = v + ((size_t)b * SEQN) * DIM;
    float v00 = vb[(size_t)k0 * DIM + dim];
    float v01 = vb[(size_t)(k0 + 1) * DIM + dim];
    float v08 = vb[(size_t)(k0 + 8) * DIM + dim];
    float v09 = vb[(size_t)(k0 + 9) * DIM + dim];
    uint2 bf = {packh(v00, v01), packh(v08, v09)};
    unsigned char* base = g_VF + ((size_t)(b * 32 + tile)) * 16384;
    *(uint2*)(base + (kc * 16 + nt) * 256 + lane * 8) = bf;
}

__global__ void prep_all(const float* __restrict__ q, const float* __restrict__ k,
                         const float* __restrict__ v) {
    int blk = blockIdx.x;
    if (blk < 2048)       prep_q_body(q, blk * 256 + threadIdx.x);
    else if (blk < 6144)  prep_k_body(k, (blk - 2048) * 256 + threadIdx.x);
    else                  prep_v_body(v, (blk - 6144) * 256 + threadIdx.x);
}

// ---------------- main attention kernel ----------------
// 4 warps/CTA, 2 CTAs/SM, Q in registers. Key-tile order staggered by
// ((bid>>2)&1)*16 so co-resident CTAs (bid, bid+148) run 16 tiles out of phase.
#define SK_OFF 0
#define SV_OFF 65536
#define SMEM_BYTES 114688   // x2 CTAs = 224KB <= 227KB

__global__ __launch_bounds__(NTHREADS, 2)
void attn_mma_2cta(float* __restrict__ o) {
    extern __shared__ unsigned char sm[];
    const int tid = threadIdx.x, warp = tid >> 5, lane = tid & 31;
    const int g = lane >> 2, t = lane & 3;
    const int b = blockIdx.y, bx = blockIdx.x;
    const int bid = b * 32 + bx;
    const int start = ((bid >> 2) & 1) * 16;   // deterministic phase stagger
    const uint32_t sbase = smem_u32(sm);

    // ---- stage K(start), V(start) ----
    {
        const unsigned char* gk = g_KF + ((size_t)(b * 32 + start)) * 32768;
        const unsigned char* gv = g_VF + ((size_t)(b * 32 + start)) * 16384;
        #pragma unroll
        for (int i = 0; i < 16; ++i)
            cp16(sbase + SK_OFF + (i * 128 + tid) * 16, gk + (size_t)(i * 128 + tid) * 16);
        #pragma unroll
        for (int i = 0; i < 8; ++i)
            cp16(sbase + SV_OFF + (i * 128 + tid) * 16, gv + (size_t)(i * 128 + tid) * 16);
        asm volatile("cp.async.commit_group;");
    }

    // ---- Q fragments -> registers ----
    uint4 QA[2][8];
    {
        const uint4* gq = reinterpret_cast<const uint4*>(
            g_QF + ((size_t)(b * 128 + bx * 4 + warp)) * 8192);
        #pragma unroll
        for (int hl = 0; hl < 2; ++hl)
            #pragma unroll
            for (int kt = 0; kt < 8; ++kt)
                QA[hl][kt] = gq[(hl * 8 + kt) * 32 + lane];
    }

    float O[16][4];
    #pragma unroll
    for (int n = 0; n < 16; ++n)
        #pragma unroll
        for (int j = 0; j < 4; ++j) O[n][j] = 0.0f;
    float M0 = -1e30f, M1 = -1e30f, L0 = 0.0f, L1 = 0.0f;
    uint32_t Pf[8][2];

    int vprev = 2, vcur = 0, vnext = 1;

    for (int it = 0; it < NKT; ++it) {
        asm volatile("cp.async.wait_group 0;");
        __syncthreads();

        if (it + 1 < NKT) {
            int ktn = (it + 1 + start) & 31;
            const unsigned char* gk = g_KF + ((size_t)(b * 32 + ktn)) * 32768;
            const unsigned char* gv = g_VF + ((size_t)(b * 32 + ktn)) * 16384;
            uint32_t sk = sbase + SK_OFF + (((it + 1) & 1) ? 32768u : 0u);
            uint32_t sv = sbase + SV_OFF + (uint32_t)vnext * 16384u;
            #pragma unroll
            for (int i = 0; i < 16; ++i)
                cp16(sk + (i * 128 + tid) * 16, gk + (size_t)(i * 128 + tid) * 16);
            #pragma unroll
            for (int i = 0; i < 8; ++i)
                cp16(sv + (i * 128 + tid) * 16, gv + (size_t)(i * 128 + tid) * 16);
            asm volatile("cp.async.commit_group;");
        }

        const unsigned char* skf = sm + SK_OFF + ((it & 1) ? 32768 : 0);

        // ---- QK(t): S' = (Qh+Ql)*K'h + Qh*K'l ----
        float c[8][4];
        #pragma unroll
        for (int n = 0; n < 8; ++n)
            #pragma unroll
            for (int j = 0; j < 4; ++j) c[n][j] = 0.0f;

        #pragma unroll
        for (int kt = 0; kt < 8; ++kt) {
            #pragma unroll
            for (int nt = 0; nt < 8; ++nt) {
                uint2 bh = *(const uint2*)(skf + ((0 * 8 + kt) * 8 + nt) * 256 + lane * 8);
                uint2 bl = *(const uint2*)(skf + ((1 * 8 + kt) * 8 + nt) * 256 + lane * 8);
                mma16816(c[nt], (const uint32_t*)&QA[0][kt], (const uint32_t*)&bh);
                mma16816(c[nt], (const uint32_t*)&QA[0][kt], (const uint32_t*)&bl);
                mma16816(c[nt], (const uint32_t*)&QA[1][kt], (const uint32_t*)&bh);
            }
        }

        // ---- PV(t-1): overlaps softmax below ----
        if (it > 0) {
            const unsigned char* svf = sm + SV_OFF + vprev * 16384;
            #pragma unroll
            for (int kc = 0; kc < 4; ++kc) {
                uint32_t ap[4] = {Pf[2 * kc][0], Pf[2 * kc][1],
                                  Pf[2 * kc + 1][0], Pf[2 * kc + 1][1]};
                #pragma unroll
                for (int nt = 0; nt < 16; ++nt) {
                    uint2 bv = *(const uint2*)(svf + (kc * 16 + nt) * 256 + lane * 8);
                    mma16816(O[nt], ap, (const uint32_t*)&bv);
                }
            }
        }

        // ---- softmax(t) in log2 domain ----
        float mx0 = -1e30f, mx1 = -1e30f;
        #pragma unroll
        for (int n = 0; n < 8; ++n) {
            mx0 = fmaxf(mx0, fmaxf(c[n][0], c[n][1]));
            mx1 = fmaxf(mx1, fmaxf(c[n][2], c[n][3]));
        }
        mx0 = fmaxf(mx0, __shfl_xor_sync(0xffffffffu, mx0, 1));
        mx0 = fmaxf(mx0, __shfl_xor_sync(0xffffffffu, mx0, 2));
        mx1 = fmaxf(mx1, __shfl_xor_sync(0xffffffffu, mx1, 1));
        mx1 = fmaxf(mx1, __shfl_xor_sync(0xffffffffu, mx1, 2));
        float mn0 = fmaxf(M0, mx0), mn1 = fmaxf(M1, mx1);
        float al0 = ex2(M0 - mn0), al1 = ex2(M1 - mn1);
        M0 = mn0; M1 = mn1;

        float s0 = 0.0f, s1 = 0.0f;
        #pragma unroll
        for (int n = 0; n < 8; ++n) {
            float p0 = ex2(c[n][0] - mn0), p1 = ex2(c[n][1] - mn0);
            float p2 = ex2(c[n][2] - mn1), p3 = ex2(c[n][3] - mn1);
            s0 += p0 + p1; s1 += p2 + p3;
            Pf[n][0] = packh(p0, p1);
            Pf[n][1] = packh(p2, p3);
        }
        s0 += __shfl_xor_sync(0xffffffffu, s0, 1);
        s0 += __shfl_xor_sync(0xffffffffu, s0, 2);
        s1 += __shfl_xor_sync(0xffffffffu, s1, 1);
        s1 += __shfl_xor_sync(0xffffffffu, s1, 2);
        L0 = L0 * al0 + s0;
        L1 = L1 * al1 + s1;

        // skip the O rescale when max unchanged for every lane (ex2(0)==1 exact)
        if (!__all_sync(0xffffffffu, (al0 == 1.0f) & (al1 == 1.0f))) {
            #pragma unroll
            for (int n = 0; n < 16; ++n) {
                O[n][0] *= al0; O[n][1] *= al0;
                O[n][2] *= al1; O[n][3] *= al1;
            }
        }

        int tmp = vprev; vprev = vcur; vcur = vnext; vnext = tmp;
    }

    // ---- tail: PV(last) ----
    {
        const unsigned char* svf = sm + SV_OFF + vprev * 16384;
        #pragma unroll
        for (int kc = 0; kc < 4; ++kc) {
            uint32_t ap[4] = {Pf[2 * kc][0], Pf[2 * kc][1],
                              Pf[2 * kc + 1][0], Pf[2 * kc + 1][1]};
            #pragma unroll
            for (int nt = 0; nt < 16; ++nt) {
                uint2 bv = *(const uint2*)(svf + (kc * 16 + nt) * 256 + lane * 8);
                mma16816(O[nt], ap, (const uint32_t*)&bv);
            }
        }
    }

    // ---- epilogue ----
    float inv0 = 1.0f / L0, inv1 = 1.0f / L1;
    int row0 = bx * TQ + warp * 16 + g;
    float* ob = o + ((size_t)b * SEQN + row0) * DIM;
    #pragma unroll
    for (int nt = 0; nt < 16; ++nt) {
        int d0 = nt * 8 + t * 2;
        float2 r0 = {O[nt][0] * inv0, O[nt][1] * inv0};
        float2 r1 = {O[nt][2] * inv1, O[nt][3] * inv1};
        *(float2*)(ob + d0) = r0;
        *(float2*)(ob + (size_t)8 * DIM + d0) = r1;
    }
}

extern "C" void kernel_launch(void* const* d_in, const int* in_sizes, int n_in,
                              void* d_out, int out_size) {
    (void)in_sizes; (void)n_in; (void)out_size;
    const float* q = (const float*)d_in[0];
    const float* k = (const float*)d_in[1];
    const float* v = (const float*)d_in[2];
    float* o = (float*)d_out;

    prep_all<<<10240, 256>>>(q, k, v);

    cudaFuncSetAttribute(attn_mma_2cta,
                         cudaFuncAttributeMaxDynamicSharedMemorySize, SMEM_BYTES);
    dim3 grid(SEQN / TQ, BATCH);   // 32 x 16 = 512 CTAs, 2 per SM
    attn_mma_2cta<<<grid, NTHREADS, SMEM_BYTES>>>(o);
}

// round 13
// speedup vs baseline: 1.0520x; 1.0520x over previous
#include <cuda_runtime.h>
#include <cuda_fp16.h>
#include <cstdint>
#include <cstddef>

#define BATCH 16
#define SEQN 2048
#define DIM 128
#define TQ 64
#define TK 64
#define NKT (SEQN / TK)   // 32
#define NTHREADS 128
#define LOG2E 1.4426950408889634f

// ---------------- scratch (fragment-ordered fp16 copies) ----------------
__device__ __align__(16) unsigned char g_QF[(size_t)16 * 128 * 8192];
__device__ __align__(16) unsigned char g_KF[(size_t)16 * 32 * 32768];
__device__ __align__(16) unsigned char g_VF[(size_t)16 * 32 * 16384];

__device__ __forceinline__ uint32_t packh(float x, float y) {
    __half2 h = __floats2half2_rn(x, y);
    return *reinterpret_cast<uint32_t*>(&h);
}
__device__ __forceinline__ void split(float x, float& hi, float& lo) {
    __half h = __float2half_rn(x);
    hi = __half2float(h);
    lo = x - hi;
}
__device__ __forceinline__ float ex2(float x) {
    float r; asm("ex2.approx.f32 %0, %1;" : "=f"(r) : "f"(x)); return r;
}

__device__ __forceinline__ void mma16816(float* c, const uint32_t* a, const uint32_t* b) {
    asm volatile(
        "mma.sync.aligned.m16n8k16.row.col.f32.f16.f16.f32 "
        "{%0,%1,%2,%3}, {%4,%5,%6,%7}, {%8,%9}, {%0,%1,%2,%3};"
        : "+f"(c[0]), "+f"(c[1]), "+f"(c[2]), "+f"(c[3])
        : "r"(a[0]), "r"(a[1]), "r"(a[2]), "r"(a[3]), "r"(b[0]), "r"(b[1]));
}

__device__ __forceinline__ void cp16(uint32_t saddr, const void* gaddr) {
    asm volatile("cp.async.cg.shared.global [%0], [%1], 16;" :: "r"(saddr), "l"(gaddr));
}
__device__ __forceinline__ uint32_t smem_u32(const void* p) {
    uint32_t a;
    asm("{ .reg .u64 t; cvta.to.shared.u64 t, %1; cvt.u32.u64 %0, t; }" : "=r"(a) : "l"(p));
    return a;
}

// ---------------- fused prep kernel (proven) ----------------

__device__ __forceinline__ void prep_q_body(const float* __restrict__ q, int tid) {
    int lane = tid & 31, kt = (tid >> 5) & 7, qt = (tid >> 8) & 127, b = tid >> 15;
    int g = lane >> 2, t = lane & 3;
    int row = qt * 16 + g, d0 = kt * 16 + t * 2;
    const float* qb = q + ((size_t)b * SEQN) * DIM;
    float2 x00 = *(const float2*)(qb + (size_t)row * DIM + d0);
    float2 x10 = *(const float2*)(qb + (size_t)(row + 8) * DIM + d0);
    float2 x01 = *(const float2*)(qb + (size_t)row * DIM + d0 + 8);
    float2 x11 = *(const float2*)(qb + (size_t)(row + 8) * DIM + d0 + 8);
    uint4 hi, lo;
    float l00x, l00y, l10x, l10y, l01x, l01y, l11x, l11y;
    float h00x, h00y, h10x, h10y, h01x, h01y, h11x, h11y;
    split(x00.x, h00x, l00x); split(x00.y, h00y, l00y);
    split(x10.x, h10x, l10x); split(x10.y, h10y, l10y);
    split(x01.x, h01x, l01x); split(x01.y, h01y, l01y);
    split(x11.x, h11x, l11x); split(x11.y, h11y, l11y);
    hi.x = packh(h00x, h00y); hi.y = packh(h10x, h10y);
    hi.z = packh(h01x, h01y); hi.w = packh(h11x, h11y);
    lo.x = packh(l00x, l00y); lo.y = packh(l10x, l10y);
    lo.z = packh(l01x, l01y); lo.w = packh(l11x, l11y);
    unsigned char* base = g_QF + ((size_t)(b * 128 + qt)) * 8192;
    *(uint4*)(base + (0 * 8 + kt) * 512 + lane * 16) = hi;
    *(uint4*)(base + (1 * 8 + kt) * 512 + lane * 16) = lo;
}

__device__ __forceinline__ void prep_k_body(const float* __restrict__ k, int tid) {
    int lane = tid & 31, nt = (tid >> 5) & 7, kt = (tid >> 8) & 7,
        tile = (tid >> 11) & 31, b = tid >> 16;
    int g = lane >> 2, t = lane & 3;
    int key = tile * 64 + nt * 8 + g, d0 = kt * 16 + t * 2;
    const float* kb = k + ((size_t)b * SEQN) * DIM;
    float2 f0 = *(const float2*)(kb + (size_t)key * DIM + d0);
    float2 f1 = *(const float2*)(kb + (size_t)key * DIM + d0 + 8);
    f0.x *= LOG2E; f0.y *= LOG2E; f1.x *= LOG2E; f1.y *= LOG2E;
    float h0x, l0x, h0y, l0y, h1x, l1x, h1y, l1y;
    split(f0.x, h0x, l0x); split(f0.y, h0y, l0y);
    split(f1.x, h1x, l1x); split(f1.y, h1y, l1y);
    uint2 hi = {packh(h0x, h0y), packh(h1x, h1y)};
    uint2 lo = {packh(l0x, l0y), packh(l1x, l1y)};
    unsigned char* base = g_KF + ((size_t)(b * 32 + tile)) * 32768;
    *(uint2*)(base + ((0 * 8 + kt) * 8 + nt) * 256 + lane * 8) = hi;
    *(uint2*)(base + ((1 * 8 + kt) * 8 + nt) * 256 + lane * 8) = lo;
}

__device__ __forceinline__ void prep_v_body(const float* __restrict__ v, int tid) {
    int lane = tid & 31, nt = (tid >> 5) & 15, kc = (tid >> 9) & 3,
        tile = (tid >> 11) & 31, b = tid >> 16;
    int g = lane >> 2, t = lane & 3;
    int k0 = tile * 64 + kc * 16 + t * 2, dim = nt * 8 + g;
    const float* vb = v + ((size_t)b * SEQN) * DIM;
    float v00 = vb[(size_t)k0 * DIM + dim];
    float v01 = vb[(size_t)(k0 + 1) * DIM + dim];
    float v08 = vb[(size_t)(k0 + 8) * DIM + dim];
    float v09 = vb[(size_t)(k0 + 9) * DIM + dim];
    uint2 bf = {packh(v00, v01), packh(v08, v09)};
    unsigned char* base = g_VF + ((size_t)(b * 32 + tile)) * 16384;
    *(uint2*)(base + (kc * 16 + nt) * 256 + lane * 8) = bf;
}

__global__ void prep_all(const float* __restrict__ q, const float* __restrict__ k,
                         const float* __restrict__ v) {
    int blk = blockIdx.x;
    if (blk < 2048)       prep_q_body(q, blk * 256 + threadIdx.x);
    else if (blk < 6144)  prep_k_body(k, (blk - 2048) * 256 + threadIdx.x);
    else                  prep_v_body(v, (blk - 6144) * 256 + threadIdx.x);
}

// ---------------- main attention kernel ----------------
// 4 warps/CTA, 2 CTAs/SM, Q in registers (R11 structure).
// Softmax: -mu baked into QK accumulator init; hysteresis bump (delta=8);
// L via constant-ones MMA column.
#define SK_OFF 0
#define SV_OFF 65536
#define SMEM_BYTES 114688   // x2 CTAs = 224KB <= 227KB

__global__ __launch_bounds__(NTHREADS, 2)
void attn_mma_2cta(float* __restrict__ o) {
    extern __shared__ unsigned char sm[];
    const int tid = threadIdx.x, warp = tid >> 5, lane = tid & 31;
    const int g = lane >> 2, t = lane & 3;
    const int b = blockIdx.y, bx = blockIdx.x;
    const uint32_t sbase = smem_u32(sm);

    // ---- stage K(0), V(0) ----
    {
        const unsigned char* gk = g_KF + ((size_t)(b * 32 + 0)) * 32768;
        const unsigned char* gv = g_VF + ((size_t)(b * 32 + 0)) * 16384;
        #pragma unroll
        for (int i = 0; i < 16; ++i)
            cp16(sbase + SK_OFF + (i * 128 + tid) * 16, gk + (size_t)(i * 128 + tid) * 16);
        #pragma unroll
        for (int i = 0; i < 8; ++i)
            cp16(sbase + SV_OFF + (i * 128 + tid) * 16, gv + (size_t)(i * 128 + tid) * 16);
        asm volatile("cp.async.commit_group;");
    }

    // ---- Q fragments -> registers ----
    uint4 QA[2][8];
    {
        const uint4* gq = reinterpret_cast<const uint4*>(
            g_QF + ((size_t)(b * 128 + bx * 4 + warp)) * 8192);
        #pragma unroll
        for (int hl = 0; hl < 2; ++hl)
            #pragma unroll
            for (int kt = 0; kt < 8; ++kt)
                QA[hl][kt] = gq[(hl * 8 + kt) * 32 + lane];
    }

    float O[16][4];
    #pragma unroll
    for (int n = 0; n < 16; ++n)
        #pragma unroll
        for (int j = 0; j < 4; ++j) O[n][j] = 0.0f;
    float OL[4] = {0.0f, 0.0f, 0.0f, 0.0f};   // L accumulator (ones-MMA)
    float nm0 = 0.0f, nm1 = 0.0f;             // -mu per row (mu init 0: c = S exactly)
    uint32_t Pf[8][2];
    const uint32_t ones[2] = {0x3C003C00u, 0x3C003C00u};   // fp16 1.0 x4

    int vprev = 2, vcur = 0, vnext = 1;

    for (int it = 0; it < NKT; ++it) {
        asm volatile("cp.async.wait_group 0;");
        __syncthreads();

        if (it + 1 < NKT) {
            const unsigned char* gk = g_KF + ((size_t)(b * 32 + it + 1)) * 32768;
            const unsigned char* gv = g_VF + ((size_t)(b * 32 + it + 1)) * 16384;
            uint32_t sk = sbase + SK_OFF + (((it + 1) & 1) ? 32768u : 0u);
            uint32_t sv = sbase + SV_OFF + (uint32_t)vnext * 16384u;
            #pragma unroll
            for (int i = 0; i < 16; ++i)
                cp16(sk + (i * 128 + tid) * 16, gk + (size_t)(i * 128 + tid) * 16);
            #pragma unroll
            for (int i = 0; i < 8; ++i)
                cp16(sv + (i * 128 + tid) * 16, gv + (size_t)(i * 128 + tid) * 16);
            asm volatile("cp.async.commit_group;");
        }

        const unsigned char* skf = sm + SK_OFF + ((it & 1) ? 32768 : 0);

        // ---- QK(t): c = -mu + S'  (mu baked into accumulator init) ----
        float c[8][4];
        #pragma unroll
        for (int n = 0; n < 8; ++n) {
            c[n][0] = nm0; c[n][1] = nm0;
            c[n][2] = nm1; c[n][3] = nm1;
        }

        #pragma unroll
        for (int kt = 0; kt < 8; ++kt) {
            #pragma unroll
            for (int nt = 0; nt < 8; ++nt) {
                uint2 bh = *(const uint2*)(skf + ((0 * 8 + kt) * 8 + nt) * 256 + lane * 8);
                uint2 bl = *(const uint2*)(skf + ((1 * 8 + kt) * 8 + nt) * 256 + lane * 8);
                mma16816(c[nt], (const uint32_t*)&QA[0][kt], (const uint32_t*)&bh);
                mma16816(c[nt], (const uint32_t*)&QA[0][kt], (const uint32_t*)&bl);
                mma16816(c[nt], (const uint32_t*)&QA[1][kt], (const uint32_t*)&bh);
            }
        }

        // ---- PV(t-1) + L(t-1): overlaps softmax below ----
        if (it > 0) {
            const unsigned char* svf = sm + SV_OFF + vprev * 16384;
            #pragma unroll
            for (int kc = 0; kc < 4; ++kc) {
                uint32_t ap[4] = {Pf[2 * kc][0], Pf[2 * kc][1],
                                  Pf[2 * kc + 1][0], Pf[2 * kc + 1][1]};
                #pragma unroll
                for (int nt = 0; nt < 16; ++nt) {
                    uint2 bv = *(const uint2*)(svf + (kc * 16 + nt) * 256 + lane * 8);
                    mma16816(O[nt], ap, (const uint32_t*)&bv);
                }
                mma16816(OL, ap, ones);   // row-sum of P -> L
            }
        }

        // ---- softmax(t): hysteresis-mu, steady path has no FADD/rescale ----
        float mx0 = fmaxf(fmaxf(c[0][0], c[0][1]), fmaxf(c[1][0], c[1][1]));
        float mx1 = fmaxf(fmaxf(c[0][2], c[0][3]), fmaxf(c[1][2], c[1][3]));
        #pragma unroll
        for (int n = 2; n < 8; ++n) {
            mx0 = fmaxf(mx0, fmaxf(c[n][0], c[n][1]));
            mx1 = fmaxf(mx1, fmaxf(c[n][2], c[n][3]));
        }
        mx0 = fmaxf(mx0, __shfl_xor_sync(0xffffffffu, mx0, 1));
        mx0 = fmaxf(mx0, __shfl_xor_sync(0xffffffffu, mx0, 2));
        mx1 = fmaxf(mx1, __shfl_xor_sync(0xffffffffu, mx1, 1));
        mx1 = fmaxf(mx1, __shfl_xor_sync(0xffffffffu, mx1, 2));

        if (__any_sync(0xffffffffu, fmaxf(mx0, mx1) > 8.0f)) {
            // bump rows whose local max exceeded mu by >8
            float d0 = (mx0 > 8.0f) ? mx0 : 0.0f;
            float d1 = (mx1 > 8.0f) ? mx1 : 0.0f;
            nm0 -= d0; nm1 -= d1;
            float al0 = ex2(-d0), al1 = ex2(-d1);
            #pragma unroll
            for (int n = 0; n < 8; ++n) {
                c[n][0] -= d0; c[n][1] -= d0;
                c[n][2] -= d1; c[n][3] -= d1;
            }
            #pragma unroll
            for (int n = 0; n < 16; ++n) {
                O[n][0] *= al0; O[n][1] *= al0;
                O[n][2] *= al1; O[n][3] *= al1;
            }
            OL[0] *= al0; OL[1] *= al0; OL[2] *= al1; OL[3] *= al1;
        }

        #pragma unroll
        for (int n = 0; n < 8; ++n) {
            float p0 = ex2(c[n][0]), p1 = ex2(c[n][1]);
            float p2 = ex2(c[n][2]), p3 = ex2(c[n][3]);
            Pf[n][0] = packh(p0, p1);
            Pf[n][1] = packh(p2, p3);
        }

        int tmp = vprev; vprev = vcur; vcur = vnext; vnext = tmp;
    }

    // ---- tail: PV(last) + L(last) ----
    {
        const unsigned char* svf = sm + SV_OFF + vprev * 16384;
        #pragma unroll
        for (int kc = 0; kc < 4; ++kc) {
            uint32_t ap[4] = {Pf[2 * kc][0], Pf[2 * kc][1],
                              Pf[2 * kc + 1][0], Pf[2 * kc + 1][1]};
            #pragma unroll
            for (int nt = 0; nt < 16; ++nt) {
                uint2 bv = *(const uint2*)(svf + (kc * 16 + nt) * 256 + lane * 8);
                mma16816(O[nt], ap, (const uint32_t*)&bv);
            }
            mma16816(OL, ap, ones);
        }
    }

    // ---- epilogue: L read directly from the ones-MMA accumulator ----
    float inv0 = 1.0f / OL[0], inv1 = 1.0f / OL[2];
    int row0 = bx * TQ + warp * 16 + g;
    float* ob = o + ((size_t)b * SEQN + row0) * DIM;
    #pragma unroll
    for (int nt = 0; nt < 16; ++nt) {
        int d0 = nt * 8 + t * 2;
        float2 r0 = {O[nt][0] * inv0, O[nt][1] * inv0};
        float2 r1 = {O[nt][2] * inv1, O[nt][3] * inv1};
        *(float2*)(ob + d0) = r0;
        *(float2*)(ob + (size_t)8 * DIM + d0) = r1;
    }
}

extern "C" void kernel_launch(void* const* d_in, const int* in_sizes, int n_in,
                              void* d_out, int out_size) {
    (void)in_sizes; (void)n_in; (void)out_size;
    const float* q = (const float*)d_in[0];
    const float* k = (const float*)d_in[1];
    const float* v = (const float*)d_in[2];
    float* o = (float*)d_out;

    prep_all<<<10240, 256>>>(q, k, v);

    cudaFuncSetAttribute(attn_mma_2cta,
                         cudaFuncAttributeMaxDynamicSharedMemorySize, SMEM_BYTES);
    dim3 grid(SEQN / TQ, BATCH);   // 32 x 16 = 512 CTAs, 2 per SM
    attn_mma_2cta<<<grid, NTHREADS, SMEM_BYTES>>>(o);
}

// round 16
// speedup vs baseline: 1.0529x; 1.0008x over previous
#include <cuda_runtime.h>
#include <cuda_fp16.h>
#include <cstdint>
#include <cstddef>

#define BATCH 16
#define SEQN 2048
#define DIM 128
#define TQ 64
#define TK 64
#define NKT (SEQN / TK)   // 32
#define NTHREADS 128
#define LOG2E 1.4426950408889634f

// ---------------- scratch (fragment-ordered fp16 copies) ----------------
__device__ __align__(16) unsigned char g_QF[(size_t)16 * 128 * 8192];
__device__ __align__(16) unsigned char g_KF[(size_t)16 * 32 * 32768];
__device__ __align__(16) unsigned char g_VF[(size_t)16 * 32 * 16384];

__device__ __forceinline__ uint32_t packh(float x, float y) {
    __half2 h = __floats2half2_rn(x, y);
    return *reinterpret_cast<uint32_t*>(&h);
}
__device__ __forceinline__ void split(float x, float& hi, float& lo) {
    __half h = __float2half_rn(x);
    hi = __half2float(h);
    lo = x - hi;
}
__device__ __forceinline__ float ex2(float x) {
    float r; asm("ex2.approx.f32 %0, %1;" : "=f"(r) : "f"(x)); return r;
}

__device__ __forceinline__ void mma16816(float* c, const uint32_t* a, const uint32_t* b) {
    asm volatile(
        "mma.sync.aligned.m16n8k16.row.col.f32.f16.f16.f32 "
        "{%0,%1,%2,%3}, {%4,%5,%6,%7}, {%8,%9}, {%0,%1,%2,%3};"
        : "+f"(c[0]), "+f"(c[1]), "+f"(c[2]), "+f"(c[3])
        : "r"(a[0]), "r"(a[1]), "r"(a[2]), "r"(a[3]), "r"(b[0]), "r"(b[1]));
}

__device__ __forceinline__ void cp16(uint32_t saddr, const void* gaddr) {
    asm volatile("cp.async.cg.shared.global [%0], [%1], 16;" :: "r"(saddr), "l"(gaddr));
}
__device__ __forceinline__ uint32_t smem_u32(const void* p) {
    uint32_t a;
    asm("{ .reg .u64 t; cvta.to.shared.u64 t, %1; cvt.u32.u64 %0, t; }" : "=r"(a) : "l"(p));
    return a;
}

// ---------------- fused prep kernel (proven) ----------------

__device__ __forceinline__ void prep_q_body(const float* __restrict__ q, int tid) {
    int lane = tid & 31, kt = (tid >> 5) & 7, qt = (tid >> 8) & 127, b = tid >> 15;
    int g = lane >> 2, t = lane & 3;
    int row = qt * 16 + g, d0 = kt * 16 + t * 2;
    const float* qb = q + ((size_t)b * SEQN) * DIM;
    float2 x00 = *(const float2*)(qb + (size_t)row * DIM + d0);
    float2 x10 = *(const float2*)(qb + (size_t)(row + 8) * DIM + d0);
    float2 x01 = *(const float2*)(qb + (size_t)row * DIM + d0 + 8);
    float2 x11 = *(const float2*)(qb + (size_t)(row + 8) * DIM + d0 + 8);
    uint4 hi, lo;
    float l00x, l00y, l10x, l10y, l01x, l01y, l11x, l11y;
    float h00x, h00y, h10x, h10y, h01x, h01y, h11x, h11y;
    split(x00.x, h00x, l00x); split(x00.y, h00y, l00y);
    split(x10.x, h10x, l10x); split(x10.y, h10y, l10y);
    split(x01.x, h01x, l01x); split(x01.y, h01y, l01y);
    split(x11.x, h11x, l11x); split(x11.y, h11y, l11y);
    hi.x = packh(h00x, h00y); hi.y = packh(h10x, h10y);
    hi.z = packh(h01x, h01y); hi.w = packh(h11x, h11y);
    lo.x = packh(l00x, l00y); lo.y = packh(l10x, l10y);
    lo.z = packh(l01x, l01y); lo.w = packh(l11x, l11y);
    unsigned char* base = g_QF + ((size_t)(b * 128 + qt)) * 8192;
    *(uint4*)(base + (0 * 8 + kt) * 512 + lane * 16) = hi;
    *(uint4*)(base + (1 * 8 + kt) * 512 + lane * 16) = lo;
}

__device__ __forceinline__ void prep_k_body(const float* __restrict__ k, int tid) {
    int lane = tid & 31, nt = (tid >> 5) & 7, kt = (tid >> 8) & 7,
        tile = (tid >> 11) & 31, b = tid >> 16;
    int g = lane >> 2, t = lane & 3;
    int key = tile * 64 + nt * 8 + g, d0 = kt * 16 + t * 2;
    const float* kb = k + ((size_t)b * SEQN) * DIM;
    float2 f0 = *(const float2*)(kb + (size_t)key * DIM + d0);
    float2 f1 = *(const float2*)(kb + (size_t)key * DIM + d0 + 8);
    f0.x *= LOG2E; f0.y *= LOG2E; f1.x *= LOG2E; f1.y *= LOG2E;
    float h0x, l0x, h0y, l0y, h1x, l1x, h1y, l1y;
    split(f0.x, h0x, l0x); split(f0.y, h0y, l0y);
    split(f1.x, h1x, l1x); split(f1.y, h1y, l1y);
    uint2 hi = {packh(h0x, h0y), packh(h1x, h1y)};
    uint2 lo = {packh(l0x, l0y), packh(l1x, l1y)};
    unsigned char* base = g_KF + ((size_t)(b * 32 + tile)) * 32768;
    *(uint2*)(base + ((0 * 8 + kt) * 8 + nt) * 256 + lane * 8) = hi;
    *(uint2*)(base + ((1 * 8 + kt) * 8 + nt) * 256 + lane * 8) = lo;
}

__device__ __forceinline__ void prep_v_body(const float* __restrict__ v, int tid) {
    int lane = tid & 31, nt = (tid >> 5) & 15, kc = (tid >> 9) & 3,
        tile = (tid >> 11) & 31, b = tid >> 16;
    int g = lane >> 2, t = lane & 3;
    int k0 = tile * 64 + kc * 16 + t * 2, dim = nt * 8 + g;
    const float* vb = v + ((size_t)b * SEQN) * DIM;
    float v00 = vb[(size_t)k0 * DIM + dim];
    float v01 = vb[(size_t)(k0 + 1) * DIM + dim];
    float v08 = vb[(size_t)(k0 + 8) * DIM + dim];
    float v09 = vb[(size_t)(k0 + 9) * DIM + dim];
    uint2 bf = {packh(v00, v01), packh(v08, v09)};
    unsigned char* base = g_VF + ((size_t)(b * 32 + tile)) * 16384;
    *(uint2*)(base + (kc * 16 + nt) * 256 + lane * 8) = bf;
}

__global__ void prep_all(const float* __restrict__ q, const float* __restrict__ k,
                         const float* __restrict__ v) {
    int blk = blockIdx.x;
    if (blk < 2048)       prep_q_body(q, blk * 256 + threadIdx.x);
    else if (blk < 6144)  prep_k_body(k, (blk - 2048) * 256 + threadIdx.x);
    else                  prep_v_body(v, (blk - 6144) * 256 + threadIdx.x);
}

// ---------------- main-kernel helpers (inline functions, not macros) ----------------

// QK into c, nt-pair interleaved (breaks same-accumulator MMA chains)
__device__ __forceinline__ void qk_tile(const unsigned char* skf, int lane,
                                        const uint4 QA[2][8], float c[8][4]) {
    #pragma unroll
    for (int kt = 0; kt < 8; ++kt) {
        #pragma unroll
        for (int np = 0; np < 4; ++np) {
            int n0 = 2 * np, n1 = 2 * np + 1;
            uint2 bh0 = *(const uint2*)(skf + ((0 * 8 + kt) * 8 + n0) * 256 + lane * 8);
            uint2 bh1 = *(const uint2*)(skf + ((0 * 8 + kt) * 8 + n1) * 256 + lane * 8);
            uint2 bl0 = *(const uint2*)(skf + ((1 * 8 + kt) * 8 + n0) * 256 + lane * 8);
            uint2 bl1 = *(const uint2*)(skf + ((1 * 8 + kt) * 8 + n1) * 256 + lane * 8);
            mma16816(c[n0], (const uint32_t*)&QA[0][kt], (const uint32_t*)&bh0);
            mma16816(c[n1], (const uint32_t*)&QA[0][kt], (const uint32_t*)&bh1);
            mma16816(c[n0], (const uint32_t*)&QA[0][kt], (const uint32_t*)&bl0);
            mma16816(c[n1], (const uint32_t*)&QA[0][kt], (const uint32_t*)&bl1);
            mma16816(c[n0], (const uint32_t*)&QA[1][kt], (const uint32_t*)&bh0);
            mma16816(c[n1], (const uint32_t*)&QA[1][kt], (const uint32_t*)&bh1);
        }
    }
}

// max reduce + hysteresis bump (delta=8); adjusts c and nm, reports alphas
__device__ __forceinline__ void max_bump(float c[8][4], float& nm0, float& nm1,
                                         bool& bump, float& al0, float& al1) {
    float mx0 = fmaxf(fmaxf(c[0][0], c[0][1]), fmaxf(c[1][0], c[1][1]));
    float mx1 = fmaxf(fmaxf(c[0][2], c[0][3]), fmaxf(c[1][2], c[1][3]));
    #pragma unroll
    for (int n = 2; n < 8; ++n) {
        mx0 = fmaxf(mx0, fmaxf(c[n][0], c[n][1]));
        mx1 = fmaxf(mx1, fmaxf(c[n][2], c[n][3]));
    }
    mx0 = fmaxf(mx0, __shfl_xor_sync(0xffffffffu, mx0, 1));
    mx0 = fmaxf(mx0, __shfl_xor_sync(0xffffffffu, mx0, 2));
    mx1 = fmaxf(mx1, __shfl_xor_sync(0xffffffffu, mx1, 1));
    mx1 = fmaxf(mx1, __shfl_xor_sync(0xffffffffu, mx1, 2));
    bump = __any_sync(0xffffffffu, fmaxf(mx0, mx1) > 8.0f);
    if (bump) {
        float d0 = (mx0 > 8.0f) ? mx0 : 0.0f;
        float d1 = (mx1 > 8.0f) ? mx1 : 0.0f;
        nm0 -= d0; nm1 -= d1;
        al0 = ex2(-d0); al1 = ex2(-d1);
        #pragma unroll
        for (int n = 0; n < 8; ++n) {
            c[n][0] -= d0; c[n][1] -= d0;
            c[n][2] -= d1; c[n][3] -= d1;
        }
    }
}

// ---------------- main attention kernel ----------------
// 4 warps/CTA, 2 CTAs/SM, Q in registers. Softmax(t) interleaved into the
// PV(t-1) MMA stream (kc-chunked); bump rescale deferred to after PV.
#define SK_OFF 0
#define SV_OFF 65536
#define SMEM_BYTES 114688   // x2 CTAs = 224KB <= 227KB

__global__ __launch_bounds__(NTHREADS, 2)
void attn_mma_2cta(float* __restrict__ o) {
    extern __shared__ unsigned char sm[];
    const int tid = threadIdx.x, warp = tid >> 5, lane = tid & 31;
    const int g = lane >> 2, t = lane & 3;
    const int b = blockIdx.y, bx = blockIdx.x;
    const uint32_t sbase = smem_u32(sm);

    // ---- stage K(0), V(0) ----
    {
        const unsigned char* gk = g_KF + ((size_t)(b * 32 + 0)) * 32768;
        const unsigned char* gv = g_VF + ((size_t)(b * 32 + 0)) * 16384;
        #pragma unroll
        for (int i = 0; i < 16; ++i)
            cp16(sbase + SK_OFF + (i * 128 + tid) * 16, gk + (size_t)(i * 128 + tid) * 16);
        #pragma unroll
        for (int i = 0; i < 8; ++i)
            cp16(sbase + SV_OFF + (i * 128 + tid) * 16, gv + (size_t)(i * 128 + tid) * 16);
        asm volatile("cp.async.commit_group;");
    }

    // ---- Q fragments -> registers ----
    uint4 QA[2][8];
    {
        const uint4* gq = reinterpret_cast<const uint4*>(
            g_QF + ((size_t)(b * 128 + bx * 4 + warp)) * 8192);
        #pragma unroll
        for (int hl = 0; hl < 2; ++hl)
            #pragma unroll
            for (int kt = 0; kt < 8; ++kt)
                QA[hl][kt] = gq[(hl * 8 + kt) * 32 + lane];
    }

    float O[16][4];
    #pragma unroll
    for (int n = 0; n < 16; ++n)
        #pragma unroll
        for (int j = 0; j < 4; ++j) O[n][j] = 0.0f;
    float OL[4] = {0.0f, 0.0f, 0.0f, 0.0f};
    float nm0 = 0.0f, nm1 = 0.0f;
    uint32_t Pf[8][2];
    const uint32_t ones[2] = {0x3C003C00u, 0x3C003C00u};

    int vprev = 2, vcur = 0, vnext = 1;

    // ---- peeled iteration 0: QK + softmax only (O empty, no PV/rescale) ----
    {
        asm volatile("cp.async.wait_group 0;");
        __syncthreads();
        {
            const unsigned char* gk = g_KF + ((size_t)(b * 32 + 1)) * 32768;
            const unsigned char* gv = g_VF + ((size_t)(b * 32 + 1)) * 16384;
            uint32_t sk = sbase + SK_OFF + 32768u;
            uint32_t sv = sbase + SV_OFF + (uint32_t)vnext * 16384u;
            #pragma unroll
            for (int i = 0; i < 16; ++i)
                cp16(sk + (i * 128 + tid) * 16, gk + (size_t)(i * 128 + tid) * 16);
            #pragma unroll
            for (int i = 0; i < 8; ++i)
                cp16(sv + (i * 128 + tid) * 16, gv + (size_t)(i * 128 + tid) * 16);
            asm volatile("cp.async.commit_group;");
        }
        const unsigned char* skf = sm + SK_OFF;
        float c[8][4];
        #pragma unroll
        for (int n = 0; n < 8; ++n) { c[n][0] = 0; c[n][1] = 0; c[n][2] = 0; c[n][3] = 0; }
        qk_tile(skf, lane, QA, c);
        bool bump; float al0 = 1.0f, al1 = 1.0f;
        max_bump(c, nm0, nm1, bump, al0, al1);
        (void)bump; (void)al0; (void)al1;   // O empty: rescale is a no-op
        #pragma unroll
        for (int n = 0; n < 8; ++n) {
            Pf[n][0] = packh(ex2(c[n][0]), ex2(c[n][1]));
            Pf[n][1] = packh(ex2(c[n][2]), ex2(c[n][3]));
        }
        int tmp = vprev; vprev = vcur; vcur = vnext; vnext = tmp;
    }

    // ---- main loop it = 1 .. NKT-1 ----
    for (int it = 1; it < NKT; ++it) {
        asm volatile("cp.async.wait_group 0;");
        __syncthreads();

        if (it + 1 < NKT) {
            const unsigned char* gk = g_KF + ((size_t)(b * 32 + it + 1)) * 32768;
            const unsigned char* gv = g_VF + ((size_t)(b * 32 + it + 1)) * 16384;
            uint32_t sk = sbase + SK_OFF + (((it + 1) & 1) ? 32768u : 0u);
            uint32_t sv = sbase + SV_OFF + (uint32_t)vnext * 16384u;
            #pragma unroll
            for (int i = 0; i < 16; ++i)
                cp16(sk + (i * 128 + tid) * 16, gk + (size_t)(i * 128 + tid) * 16);
            #pragma unroll
            for (int i = 0; i < 8; ++i)
                cp16(sv + (i * 128 + tid) * 16, gv + (size_t)(i * 128 + tid) * 16);
            asm volatile("cp.async.commit_group;");
        }

        const unsigned char* skf = sm + SK_OFF + ((it & 1) ? 32768 : 0);

        // QK(t): c = -mu + S'  (mu baked into accumulator init)
        float c[8][4];
        #pragma unroll
        for (int n = 0; n < 8; ++n) {
            c[n][0] = nm0; c[n][1] = nm0; c[n][2] = nm1; c[n][3] = nm1;
        }
        qk_tile(skf, lane, QA, c);

        bool bump; float al0 = 1.0f, al1 = 1.0f;
        max_bump(c, nm0, nm1, bump, al0, al1);

        // kc loop: PV(t-1) MMAs interleaved with new-P(t) for the freed rows.
        // O/OL stay at old scale through this loop (P(t-1) is old-scale);
        // rescale happens after.
        const unsigned char* svf = sm + SV_OFF + vprev * 16384;
        #pragma unroll
        for (int kc = 0; kc < 4; ++kc) {
            uint32_t ap[4] = {Pf[2 * kc][0], Pf[2 * kc][1],
                              Pf[2 * kc + 1][0], Pf[2 * kc + 1][1]};
            #pragma unroll
            for (int nt = 0; nt < 16; ++nt) {
                uint2 bv = *(const uint2*)(svf + (kc * 16 + nt) * 256 + lane * 8);
                mma16816(O[nt], ap, (const uint32_t*)&bv);
            }
            mma16816(OL, ap, ones);
            // new P for rows 2kc, 2kc+1 (post-bump c) — fills HMMA rt gaps
            Pf[2 * kc][0]     = packh(ex2(c[2 * kc][0]),     ex2(c[2 * kc][1]));
            Pf[2 * kc][1]     = packh(ex2(c[2 * kc][2]),     ex2(c[2 * kc][3]));
            Pf[2 * kc + 1][0] = packh(ex2(c[2 * kc + 1][0]), ex2(c[2 * kc + 1][1]));
            Pf[2 * kc + 1][1] = packh(ex2(c[2 * kc + 1][2]), ex2(c[2 * kc + 1][3]));
        }

        // deferred rescale (covers accumulated O including PV(t-1))
        if (bump) {
            #pragma unroll
            for (int n = 0; n < 16; ++n) {
                O[n][0] *= al0; O[n][1] *= al0;
                O[n][2] *= al1; O[n][3] *= al1;
            }
            OL[0] *= al0; OL[1] *= al0; OL[2] *= al1; OL[3] *= al1;
        }

        int tmp = vprev; vprev = vcur; vcur = vnext; vnext = tmp;
    }

    // ---- tail: PV(last) + L(last) ----
    {
        const unsigned char* svf = sm + SV_OFF + vprev * 16384;
        #pragma unroll
        for (int kc = 0; kc < 4; ++kc) {
            uint32_t ap[4] = {Pf[2 * kc][0], Pf[2 * kc][1],
                              Pf[2 * kc + 1][0], Pf[2 * kc + 1][1]};
            #pragma unroll
            for (int nt = 0; nt < 16; ++nt) {
                uint2 bv = *(const uint2*)(svf + (kc * 16 + nt) * 256 + lane * 8);
                mma16816(O[nt], ap, (const uint32_t*)&bv);
            }
            mma16816(OL, ap, ones);
        }
    }

    // ---- epilogue ----
    float inv0 = 1.0f / OL[0], inv1 = 1.0f / OL[2];
    int row0 = bx * TQ + warp * 16 + g;
    float* ob = o + ((size_t)b * SEQN + row0) * DIM;
    #pragma unroll
    for (int nt = 0; nt < 16; ++nt) {
        int d0 = nt * 8 + t * 2;
        float2 r0 = {O[nt][0] * inv0, O[nt][1] * inv0};
        float2 r1 = {O[nt][2] * inv1, O[nt][3] * inv1};
        *(float2*)(ob + d0) = r0;
        *(float2*)(ob + (size_t)8 * DIM + d0) = r1;
    }
}

extern "C" void kernel_launch(void* const* d_in, const int* in_sizes, int n_in,
                              void* d_out, int out_size) {
    (void)in_sizes; (void)n_in; (void)out_size;
    const float* q = (const float*)d_in[0];
    const float* k = (const float*)d_in[1];
    const float* v = (const float*)d_in[2];
    float* o = (float*)d_out;

    prep_all<<<10240, 256>>>(q, k, v);

    cudaFuncSetAttribute(attn_mma_2cta,
                         cudaFuncAttributeMaxDynamicSharedMemorySize, SMEM_BYTES);
    dim3 grid(SEQN / TQ, BATCH);   // 32 x 16 = 512 CTAs, 2 per SM
    attn_mma_2cta<<<grid, NTHREADS, SMEM_BYTES>>>(o);
}